// round 15
// baseline (speedup 1.0000x reference)
#include <cuda_runtime.h>
#include <cuda_fp16.h>
#include <cuda_bf16.h>
#include <cstdint>

// ============================================================================
// Problem constants
// ============================================================================
#define IN_F   4096
#define OUT_F  11008
#define TOKENS 8192

#define BM 128
#define BN 256
#define BK 64
#define KITERS (IN_F / BK)   // 64
#define STAGES 3
#define A_STAGE_BYTES 16384                 // 128 rows x 128B
#define B_STAGE_BYTES 32768                 // 256 rows x 128B
#define OFF_B (STAGES * A_STAGE_BYTES)      // 49152
#define SMEM_BYTES (STAGES * (A_STAGE_BYTES + B_STAGE_BYTES) + 1024)  // 148480

#define N_TILES (OUT_F / BN)   // 43
#define M_TILES (TOKENS / BM)  // 64
#define GROUP_N 4              // N-tiles per rasterization group (B slab 8MB in L2)

// __device__ scratch (allowed; no allocs)
__device__ __half X16g[(size_t)TOKENS * IN_F];   // 64 MB fp16 activations
__device__ __half W16g[(size_t)OUT_F * IN_F];    // 86 MB fp16 unpacked weights
__device__ float2 SBg[OUT_F];                    // packed (scale, bias)
__device__ int    wp_layout;                     // 0: uint8 raw, 1: int32, 2: bf16

// ============================================================================
// Helpers
// ============================================================================
__device__ __forceinline__ uint32_t smem_to_u32(const void* smem_ptr) {
    uint32_t addr;
    asm("{ .reg .u64 tmp; cvta.to.shared.u64 tmp, %1; cvt.u32.u64 %0, tmp; }"
        : "=r"(addr) : "l"(smem_ptr));
    return addr;
}

__device__ __forceinline__ uint32_t sw128(uint32_t off) {
    return off ^ ((off >> 3) & 0x70);
}

__device__ __forceinline__ void cp_async16(uint32_t smem_addr, const void* gptr) {
    size_t gaddr = __cvta_generic_to_global(gptr);
    asm volatile("cp.async.cg.shared.global [%0], [%1], 16;"
                 :: "r"(smem_addr), "l"(gaddr) : "memory");
}
#define CP_COMMIT()  asm volatile("cp.async.commit_group;" ::: "memory")
#define CP_WAIT_0()  asm volatile("cp.async.wait_group 0;" ::: "memory")
#define CP_WAIT_1()  asm volatile("cp.async.wait_group 1;" ::: "memory")

__device__ __forceinline__ void ldsm_x4(uint32_t* r, uint32_t addr) {
    asm volatile("ldmatrix.sync.aligned.m8n8.x4.shared.b16 {%0,%1,%2,%3}, [%4];"
                 : "=r"(r[0]), "=r"(r[1]), "=r"(r[2]), "=r"(r[3]) : "r"(addr));
}

__device__ __forceinline__ void mma16816(float* d, const uint32_t* a, const uint32_t* b) {
    asm volatile(
        "mma.sync.aligned.m16n8k16.row.col.f32.f16.f16.f32 "
        "{%0,%1,%2,%3}, {%4,%5,%6,%7}, {%8,%9}, {%0,%1,%2,%3};"
        : "+f"(d[0]), "+f"(d[1]), "+f"(d[2]), "+f"(d[3])
        : "r"(a[0]), "r"(a[1]), "r"(a[2]), "r"(a[3]), "r"(b[0]), "r"(b[1]));
}

// ============================================================================
// Fused prep: detect weight layout, identify scale vs bias, build SB table.
// Flags computed redundantly per block (cheap) -> no cross-block dependency.
// ============================================================================
__global__ void prep_meta_kernel(const unsigned* __restrict__ wp,
                                 const float* __restrict__ c0,
                                 const float* __restrict__ c1) {
    // layout detect (thread 0 of each block, stored to global once by block 0)
    bool all_small = true, all_bf16 = true;
    for (int i = 0; i < 64; i++) {
        unsigned w = wp[i];
        if (w >= 256u) all_small = false;
        unsigned hb0 = (w >> 8) & 0xFFu;
        unsigned hb1 = (w >> 24) & 0xFFu;
        bool ok0 = (hb0 == 0u) || (hb0 >= 0x3Fu && hb0 <= 0x43u);
        bool ok1 = (hb1 == 0u) || (hb1 >= 0x3Fu && hb1 <= 0x43u);
        if (!(ok0 && ok1)) all_bf16 = false;
    }
    if (blockIdx.x == 0 && threadIdx.x == 0)
        wp_layout = all_small ? 1 : (all_bf16 ? 2 : 0);

    // scale/bias disambiguation (per-block, redundant)
    int pos = 0;
    for (int i = 0; i < 256; i++) pos += (c0[i] > 0.0f) ? 1 : 0;
    const float* s = (pos == 256) ? c0 : c1;
    const float* b = (pos == 256) ? c1 : c0;

    int i = blockIdx.x * blockDim.x + threadIdx.x;
    if (i < OUT_F) SBg[i] = make_float2(s[i], b[i]);
}

// ============================================================================
// Prep 1: x fp32 -> fp16
// ============================================================================
__global__ void prep_x_kernel(const float* __restrict__ x) {
    size_t i = (size_t)blockIdx.x * blockDim.x + threadIdx.x;
    const float4* src = (const float4*)x;
    float4 a = src[i * 2 + 0];
    float4 b = src[i * 2 + 1];
    __half2 h0 = __floats2half2_rn(a.x, a.y);
    __half2 h1 = __floats2half2_rn(a.z, a.w);
    __half2 h2 = __floats2half2_rn(b.x, b.y);
    __half2 h3 = __floats2half2_rn(b.z, b.w);
    uint4 o;
    o.x = *reinterpret_cast<unsigned*>(&h0);
    o.y = *reinterpret_cast<unsigned*>(&h1);
    o.z = *reinterpret_cast<unsigned*>(&h2);
    o.w = *reinterpret_cast<unsigned*>(&h3);
    reinterpret_cast<uint4*>(X16g)[i] = o;
}

// ============================================================================
// Prep 2: unpack ternary -> fp16, layout-aware.
// Thread i handles packed bytes [4i, 4i+4) = weights [16i, 16i+16).
// ============================================================================
__global__ void prep_w_kernel(const void* __restrict__ wp) {
    size_t i = (size_t)blockIdx.x * blockDim.x + threadIdx.x;  // 2,818,048 threads
    const int layout = wp_layout;
    unsigned bytes4;
    if (layout == 0) {
        bytes4 = reinterpret_cast<const unsigned*>(wp)[i];
    } else if (layout == 1) {
        int4 v = reinterpret_cast<const int4*>(wp)[i];
        bytes4 = (unsigned)(v.x & 0xFF) | ((unsigned)(v.y & 0xFF) << 8) |
                 ((unsigned)(v.z & 0xFF) << 16) | ((unsigned)(v.w & 0xFF) << 24);
    } else {
        const __nv_bfloat16* p = reinterpret_cast<const __nv_bfloat16*>(wp) + 4 * i;
        unsigned b0 = (unsigned)__bfloat162float(p[0]);
        unsigned b1 = (unsigned)__bfloat162float(p[1]);
        unsigned b2 = (unsigned)__bfloat162float(p[2]);
        unsigned b3 = (unsigned)__bfloat162float(p[3]);
        bytes4 = b0 | (b1 << 8) | (b2 << 16) | (b3 << 24);
    }
    unsigned r32[8];
#pragma unroll
    for (int j = 0; j < 8; j++) {
        int c0 = (int)((bytes4 >> (4 * j)) & 3u) - 1;
        int c1 = (int)((bytes4 >> (4 * j + 2)) & 3u) - 1;
        __half2 ph = __halves2half2(__int2half_rn(c0), __int2half_rn(c1));
        r32[j] = *reinterpret_cast<unsigned*>(&ph);
    }
    uint4* dst = reinterpret_cast<uint4*>(W16g);
    dst[i * 2 + 0] = make_uint4(r32[0], r32[1], r32[2], r32[3]);
    dst[i * 2 + 1] = make_uint4(r32[4], r32[5], r32[6], r32[7]);
}

// ============================================================================
// Main GEMM: ldmatrix + mma.sync m16n8k16, 3-stage cp.async pipeline
//   512 threads = 16 warps (4 M x 4 N); warp tile 32x64; CTA tile 128x256x64
// ============================================================================
__global__ void __launch_bounds__(512, 1)
ternary_gemm_kernel(float* __restrict__ out) {
    extern __shared__ char smem_raw[];
    uint32_t smem_u = smem_to_u32(smem_raw);
    uint32_t base = (smem_u + 1023u) & ~1023u;

    const int tid = threadIdx.x;
    const int wid = tid >> 5;
    const int lane = tid & 31;

    // Rasterization: groups of (64 M-tiles x up to 4 N-tiles), M fastest.
    const int bid = blockIdx.x;
    const int group = bid >> 8;
    const int rem = bid & 255;
    const int m_idx = rem & (M_TILES - 1);
    const int n_idx = group * GROUP_N + (rem >> 6);
    const int m0 = m_idx * BM;
    const int n0 = n_idx * BN;

    const int wm = (wid & 3) * 32;      // warp M offset (4 x 32 = 128)
    const int wn = (wid >> 2) * 64;     // warp N offset (4 x 64 = 256)

    // ldmatrix lane address components
    const int aRow = lane & 15;
    const int aC = lane >> 4;
    const int bRow = ((lane >> 4) << 3) + (lane & 7);
    const int bC = (lane >> 3) & 1;

    uint32_t rowOffA[2], rowOffB[4];
#pragma unroll
    for (int mt = 0; mt < 2; mt++) rowOffA[mt] = (uint32_t)(wm + mt * 16 + aRow) * 128u;
#pragma unroll
    for (int np = 0; np < 4; np++) rowOffB[np] = (uint32_t)(wn + np * 16 + bRow) * 128u;

    float acc[2][8][4];
#pragma unroll
    for (int mt = 0; mt < 2; mt++)
#pragma unroll
        for (int nt = 0; nt < 8; nt++)
#pragma unroll
            for (int r = 0; r < 4; r++) acc[mt][nt][r] = 0.f;

    // cp.async loader (512 threads): rows 64/pass; A: 2 passes, B: 4 passes
    const int lrow = tid >> 3;          // 0..63
    const int lc = tid & 7;
    const __half* aGbase = X16g + (size_t)(m0 + lrow) * IN_F + lc * 8;
    const __half* bGbase = W16g + (size_t)(n0 + lrow) * IN_F + lc * 8;

    auto load_stage = [&](int it) {
        const int s = it % STAGES;
        const int k0 = it * BK;
        const uint32_t aB = base + s * A_STAGE_BYTES;
        const uint32_t bB = base + OFF_B + s * B_STAGE_BYTES;
#pragma unroll
        for (int j = 0; j < 2; j++) {
            uint32_t soff = sw128((uint32_t)(lrow + 64 * j) * 128u + (uint32_t)lc * 16u);
            cp_async16(aB + soff, aGbase + (size_t)(64 * j) * IN_F + k0);
        }
#pragma unroll
        for (int j = 0; j < 4; j++) {
            uint32_t soff = sw128((uint32_t)(lrow + 64 * j) * 128u + (uint32_t)lc * 16u);
            cp_async16(bB + soff, bGbase + (size_t)(64 * j) * IN_F + k0);
        }
        CP_COMMIT();
    };

    load_stage(0);
    load_stage(1);

    for (int i = 0; i < KITERS; i++) {
        if (i + 2 < KITERS) { CP_WAIT_1(); } else { CP_WAIT_0(); }
        __syncthreads();
        if (i + 2 < KITERS) load_stage(i + 2);

        const int s = i % STAGES;
        const uint32_t aB = base + s * A_STAGE_BYTES;
        const uint32_t bB = base + OFF_B + s * B_STAGE_BYTES;

#pragma unroll
        for (int ks = 0; ks < BK / 16; ks++) {
            uint32_t af[2][4];
#pragma unroll
            for (int mt = 0; mt < 2; mt++)
                ldsm_x4(af[mt], aB + sw128(rowOffA[mt] + (uint32_t)(ks * 2 + aC) * 16u));
            uint32_t bf[4][4];
#pragma unroll
            for (int np = 0; np < 4; np++)
                ldsm_x4(bf[np], bB + sw128(rowOffB[np] + (uint32_t)(ks * 2 + bC) * 16u));
#pragma unroll
            for (int mt = 0; mt < 2; mt++)
#pragma unroll
                for (int nt = 0; nt < 8; nt++)
                    mma16816(acc[mt][nt], af[mt], &bf[nt >> 1][(nt & 1) * 2]);
        }
    }

    // Epilogue: y = d * scale[col] + bias[col]
    const int tr = lane >> 2;
    const int tc = (lane & 3) * 2;
#pragma unroll
    for (int nt = 0; nt < 8; nt++) {
        const int col = n0 + wn + nt * 8 + tc;
        const float2 sb0 = SBg[col];
        const float2 sb1 = SBg[col + 1];
#pragma unroll
        for (int mt = 0; mt < 2; mt++) {
            const int row = m0 + wm + mt * 16 + tr;
            float2 v0, v1;
            v0.x = fmaf(acc[mt][nt][0], sb0.x, sb0.y);
            v0.y = fmaf(acc[mt][nt][1], sb1.x, sb1.y);
            v1.x = fmaf(acc[mt][nt][2], sb0.x, sb0.y);
            v1.y = fmaf(acc[mt][nt][3], sb1.x, sb1.y);
            *reinterpret_cast<float2*>(out + (size_t)row * OUT_F + col) = v0;
            *reinterpret_cast<float2*>(out + (size_t)(row + 8) * OUT_F + col) = v1;
        }
    }
}

// ============================================================================
// Launcher — inputs identified by SIZE (element counts):
//   x: 33,554,432   weight_packed: 11,272,192   scale/bias: 11,008 each
// weight_packed element type detected on-device (uint8 / int32 / bf16).
// ============================================================================
extern "C" void kernel_launch(void* const* d_in, const int* in_sizes, int n_in,
                              void* d_out, int out_size) {
    int ix = -1, iw = -1, is1 = -1, is2 = -1;
    for (int i = 0; i < n_in; i++) {
        long v = in_sizes[i];
        if (v == (long)TOKENS * IN_F)           ix = i;
        else if (v == (long)OUT_F * (IN_F / 4)) iw = i;
        else if (is1 < 0)                       is1 = i;
        else                                    is2 = i;
    }
    if (ix < 0) ix = 0;
    if (iw < 0) iw = 1;
    if (is1 < 0) is1 = 2;
    if (is2 < 0) is2 = 3;

    const float* x    = (const float*)d_in[ix];
    const void* wp    = d_in[iw];
    const float* c0   = (const float*)d_in[is1];
    const float* c1   = (const float*)d_in[is2];
    float* out        = (float*)d_out;

    prep_meta_kernel<<<(OUT_F + 255) / 256, 256>>>((const unsigned*)wp, c0, c1);
    prep_x_kernel<<<16384, 256>>>(x);
    prep_w_kernel<<<11008, 256>>>(wp);

    cudaFuncSetAttribute(ternary_gemm_kernel,
                         cudaFuncAttributeMaxDynamicSharedMemorySize, SMEM_BYTES);
    ternary_gemm_kernel<<<M_TILES * N_TILES, 512, SMEM_BYTES>>>(out);
}

// round 16
// speedup vs baseline: 1.0029x; 1.0029x over previous
#include <cuda_runtime.h>
#include <cuda_fp16.h>
#include <cuda_bf16.h>
#include <cstdint>

// ============================================================================
// Problem constants
// ============================================================================
#define IN_F   4096
#define OUT_F  11008
#define TOKENS 8192

#define BM 128
#define BN 128
#define BK 64
#define KITERS (IN_F / BK)   // 64
#define STAGES 3
#define STAGE_BYTES 16384                  // 128 rows x 128B
#define OFF_B (STAGES * STAGE_BYTES)       // 49152
#define SMEM_BYTES (2 * STAGES * STAGE_BYTES + 1024)   // 99328

#define N_TILES (OUT_F / BN)   // 86
#define M_TILES (TOKENS / BM)  // 64
#define TOTAL_TILES (M_TILES * N_TILES)  // 5504
#define GROUP_N 8              // N-tiles per rasterization group
#define GRID_GEMM 296          // 2 CTAs per SM x 148 SMs (persistent)

// Fused prep grid split
#define PX_BLOCKS 16384
#define PW_BLOCKS 11008
#define SB_BLOCKS 43
#define PREP_BLOCKS (PX_BLOCKS + PW_BLOCKS + SB_BLOCKS)

// __device__ scratch (allowed; no allocs)
__device__ __half X16g[(size_t)TOKENS * IN_F];   // 64 MB fp16 activations
__device__ __half W16g[(size_t)OUT_F * IN_F];    // 86 MB fp16 unpacked weights
__device__ float2 SBg[OUT_F];                    // packed (scale, bias)

// ============================================================================
// Helpers
// ============================================================================
__device__ __forceinline__ uint32_t smem_to_u32(const void* smem_ptr) {
    uint32_t addr;
    asm("{ .reg .u64 tmp; cvta.to.shared.u64 tmp, %1; cvt.u32.u64 %0, tmp; }"
        : "=r"(addr) : "l"(smem_ptr));
    return addr;
}

__device__ __forceinline__ uint32_t sw128(uint32_t off) {
    return off ^ ((off >> 3) & 0x70);
}

__device__ __forceinline__ void cp_async16(uint32_t smem_addr, const void* gptr) {
    size_t gaddr = __cvta_generic_to_global(gptr);
    asm volatile("cp.async.cg.shared.global [%0], [%1], 16;"
                 :: "r"(smem_addr), "l"(gaddr) : "memory");
}
#define CP_COMMIT()  asm volatile("cp.async.commit_group;" ::: "memory")
#define CP_WAIT_0()  asm volatile("cp.async.wait_group 0;" ::: "memory")
#define CP_WAIT_1()  asm volatile("cp.async.wait_group 1;" ::: "memory")

__device__ __forceinline__ void ldsm_x4(uint32_t* r, uint32_t addr) {
    asm volatile("ldmatrix.sync.aligned.m8n8.x4.shared.b16 {%0,%1,%2,%3}, [%4];"
                 : "=r"(r[0]), "=r"(r[1]), "=r"(r[2]), "=r"(r[3]) : "r"(addr));
}

__device__ __forceinline__ void mma16816(float* d, const uint32_t* a, const uint32_t* b) {
    asm volatile(
        "mma.sync.aligned.m16n8k16.row.col.f32.f16.f16.f32 "
        "{%0,%1,%2,%3}, {%4,%5,%6,%7}, {%8,%9}, {%0,%1,%2,%3};"
        : "+f"(d[0]), "+f"(d[1]), "+f"(d[2]), "+f"(d[3])
        : "r"(a[0]), "r"(a[1]), "r"(a[2]), "r"(a[3]), "r"(b[0]), "r"(b[1]));
}

// ============================================================================
// Fused prep kernel: one launch does x-convert, w-unpack, and SB table.
//   blocks [0, PX_BLOCKS)                : x fp32 -> fp16 (8 floats/thread)
//   blocks [PX_BLOCKS, PX+PW)            : weight unpack (16 w/thread)
//   blocks [PX+PW, PX+PW+SB)             : scale/bias table
// Layout/scale flags recomputed redundantly per block (cheap, race-free).
// ============================================================================
__global__ void __launch_bounds__(256)
prep_all_kernel(const float* __restrict__ x,
                const void* __restrict__ wp,
                const float* __restrict__ c0,
                const float* __restrict__ c1) {
    const int b = blockIdx.x;
    if (b < PX_BLOCKS) {
        size_t i = (size_t)b * 256 + threadIdx.x;
        const float4* src = (const float4*)x;
        float4 a = src[i * 2 + 0];
        float4 bb = src[i * 2 + 1];
        __half2 h0 = __floats2half2_rn(a.x, a.y);
        __half2 h1 = __floats2half2_rn(a.z, a.w);
        __half2 h2 = __floats2half2_rn(bb.x, bb.y);
        __half2 h3 = __floats2half2_rn(bb.z, bb.w);
        uint4 o;
        o.x = *reinterpret_cast<unsigned*>(&h0);
        o.y = *reinterpret_cast<unsigned*>(&h1);
        o.z = *reinterpret_cast<unsigned*>(&h2);
        o.w = *reinterpret_cast<unsigned*>(&h3);
        reinterpret_cast<uint4*>(X16g)[i] = o;
    } else if (b < PX_BLOCKS + PW_BLOCKS) {
        // detect weight layout (redundant per block):
        //  int32-widened: all u32 words < 256; bf16-widened: high byte of each
        //  half in {0, 0x3F..0x43}; uint8 raw: neither.
        const unsigned* w32 = (const unsigned*)wp;
        bool all_small = true, all_bf16 = true;
        for (int i = 0; i < 64; i++) {
            unsigned w = w32[i];
            if (w >= 256u) all_small = false;
            unsigned hb0 = (w >> 8) & 0xFFu;
            unsigned hb1 = (w >> 24) & 0xFFu;
            bool ok0 = (hb0 == 0u) || (hb0 >= 0x3Fu && hb0 <= 0x43u);
            bool ok1 = (hb1 == 0u) || (hb1 >= 0x3Fu && hb1 <= 0x43u);
            if (!(ok0 && ok1)) all_bf16 = false;
        }
        const int layout = all_small ? 1 : (all_bf16 ? 2 : 0);

        size_t i = (size_t)(b - PX_BLOCKS) * 256 + threadIdx.x;
        unsigned bytes4;
        if (layout == 1) {
            int4 v = reinterpret_cast<const int4*>(wp)[i];
            bytes4 = (unsigned)(v.x & 0xFF) | ((unsigned)(v.y & 0xFF) << 8) |
                     ((unsigned)(v.z & 0xFF) << 16) | ((unsigned)(v.w & 0xFF) << 24);
        } else if (layout == 2) {
            const __nv_bfloat16* p = reinterpret_cast<const __nv_bfloat16*>(wp) + 4 * i;
            unsigned b0 = (unsigned)__bfloat162float(p[0]);
            unsigned b1 = (unsigned)__bfloat162float(p[1]);
            unsigned b2 = (unsigned)__bfloat162float(p[2]);
            unsigned b3 = (unsigned)__bfloat162float(p[3]);
            bytes4 = b0 | (b1 << 8) | (b2 << 16) | (b3 << 24);
        } else {
            bytes4 = reinterpret_cast<const unsigned*>(wp)[i];
        }
        unsigned r32[8];
#pragma unroll
        for (int j = 0; j < 8; j++) {
            int v0 = (int)((bytes4 >> (4 * j)) & 3u) - 1;
            int v1 = (int)((bytes4 >> (4 * j + 2)) & 3u) - 1;
            __half2 ph = __halves2half2(__int2half_rn(v0), __int2half_rn(v1));
            r32[j] = *reinterpret_cast<unsigned*>(&ph);
        }
        uint4* dst = reinterpret_cast<uint4*>(W16g);
        dst[i * 2 + 0] = make_uint4(r32[0], r32[1], r32[2], r32[3]);
        dst[i * 2 + 1] = make_uint4(r32[4], r32[5], r32[6], r32[7]);
    } else {
        // scale/bias disambiguation (scale ~ U[0.01,0.1] all-positive)
        int pos = 0;
        for (int i = 0; i < 256; i++) pos += (c0[i] > 0.0f) ? 1 : 0;
        const float* s = (pos == 256) ? c0 : c1;
        const float* bp = (pos == 256) ? c1 : c0;
        int i = (b - PX_BLOCKS - PW_BLOCKS) * 256 + threadIdx.x;
        if (i < OUT_F) SBg[i] = make_float2(s[i], bp[i]);
    }
}

// ============================================================================
// Persistent GEMM: ldmatrix + mma.sync m16n8k16, 3-stage cp.async pipeline.
//   256 threads = 8 warps (2 M x 4 N); warp tile 64x32; CTA tile 128x128x64.
//   Each CTA walks tiles bid, bid+296, ...; next tile's first two stages are
//   pre-issued BEFORE the epilogue so the prologue hides under the stores.
// ============================================================================
__global__ void __launch_bounds__(256, 2)
ternary_gemm_kernel(float* __restrict__ out) {
    extern __shared__ char smem_raw[];
    uint32_t smem_u = smem_to_u32(smem_raw);
    uint32_t base = (smem_u + 1023u) & ~1023u;

    const int tid = threadIdx.x;
    const int wid = tid >> 5;
    const int lane = tid & 31;

    const int wm = (wid >> 2) * 64;
    const int wn = (wid & 3) * 32;

    // ldmatrix lane address components
    const int aRow = lane & 15;
    const int aC = lane >> 4;
    const int bRow = ((lane >> 4) << 3) + (lane & 7);
    const int bC = (lane >> 3) & 1;

    uint32_t rowOffA[4], rowOffB[2];
#pragma unroll
    for (int mt = 0; mt < 4; mt++) rowOffA[mt] = (uint32_t)(wm + mt * 16 + aRow) * 128u;
#pragma unroll
    for (int np = 0; np < 2; np++) rowOffB[np] = (uint32_t)(wn + np * 16 + bRow) * 128u;

    // loader mapping
    const int lrow = tid >> 3;
    const int lc = tid & 7;

    auto tile_coords = [](int t, int& m0, int& n0) {
        const int group = t >> 9;               // /(64*GROUP_N)
        const int rem = t & 511;
        const int m_idx = rem & (M_TILES - 1);
        const int n_idx = group * GROUP_N + (rem >> 6);
        m0 = m_idx * BM;
        n0 = n_idx * BN;
    };

    auto load_stage = [&](int slot, int m0, int n0, int it) {
        const int k0 = it * BK;
        const uint32_t aB = base + slot * STAGE_BYTES;
        const uint32_t bB = base + OFF_B + slot * STAGE_BYTES;
        const __half* aG = X16g + (size_t)(m0 + lrow) * IN_F + k0 + lc * 8;
        const __half* bG = W16g + (size_t)(n0 + lrow) * IN_F + k0 + lc * 8;
#pragma unroll
        for (int j = 0; j < 4; j++) {
            uint32_t soff = sw128((uint32_t)(lrow + 32 * j) * 128u + (uint32_t)lc * 16u);
            cp_async16(aB + soff, aG + (size_t)(32 * j) * IN_F);
            cp_async16(bB + soff, bG + (size_t)(32 * j) * IN_F);
        }
        CP_COMMIT();
    };

    float acc[4][4][4];
#pragma unroll
    for (int mt = 0; mt < 4; mt++)
#pragma unroll
        for (int nt = 0; nt < 4; nt++)
#pragma unroll
            for (int r = 0; r < 4; r++) acc[mt][nt][r] = 0.f;

    int t = blockIdx.x;
    if (t >= TOTAL_TILES) return;
    int m0, n0;
    tile_coords(t, m0, n0);
    int tb = 0;   // slot of iter 0 for current tile

    // prologue for first tile
    load_stage(tb, m0, n0, 0);
    load_stage((tb + 1) % STAGES, m0, n0, 1);

    while (true) {
        // -------- mainloop --------
        for (int i = 0; i < KITERS; i++) {
            if (i + 2 < KITERS) { CP_WAIT_1(); } else { CP_WAIT_0(); }
            __syncthreads();
            if (i + 2 < KITERS) load_stage((tb + i + 2) % STAGES, m0, n0, i + 2);

            const int slot = (tb + i) % STAGES;
            const uint32_t aB = base + slot * STAGE_BYTES;
            const uint32_t bB = base + OFF_B + slot * STAGE_BYTES;

#pragma unroll
            for (int ks = 0; ks < BK / 16; ks++) {
                uint32_t af[4][4];
#pragma unroll
                for (int mt = 0; mt < 4; mt++)
                    ldsm_x4(af[mt], aB + sw128(rowOffA[mt] + (uint32_t)(ks * 2 + aC) * 16u));
                uint32_t bf[2][4];
#pragma unroll
                for (int np = 0; np < 2; np++)
                    ldsm_x4(bf[np], bB + sw128(rowOffB[np] + (uint32_t)(ks * 2 + bC) * 16u));
#pragma unroll
                for (int mt = 0; mt < 4; mt++)
#pragma unroll
                    for (int nt = 0; nt < 4; nt++)
                        mma16816(acc[mt][nt], af[mt], &bf[nt >> 1][(nt & 1) * 2]);
            }
        }

        // -------- pre-issue next tile's prologue (hides under epilogue) ----
        // Safe: slots (tb+1)%3 and (tb+2)%3 were last READ in iters 61/62,
        // whose completion is guaranteed by the barrier at top of iter 63.
        // Iter-63 stragglers only read slot tb%3, which we do not touch.
        const int tn = t + GRID_GEMM;
        const int tb2 = (tb + KITERS) % STAGES;   // == (tb+1)%3
        int m0n = 0, n0n = 0;
        if (tn < TOTAL_TILES) {
            tile_coords(tn, m0n, n0n);
            load_stage(tb2, m0n, n0n, 0);
            load_stage((tb2 + 1) % STAGES, m0n, n0n, 1);
        }

        // -------- epilogue: y = d * scale[col] + bias[col] --------
        const int tr = lane >> 2;
        const int tc = (lane & 3) * 2;
#pragma unroll
        for (int nt = 0; nt < 4; nt++) {
            const int col = n0 + wn + nt * 8 + tc;
            const float2 sb0 = SBg[col];
            const float2 sb1 = SBg[col + 1];
#pragma unroll
            for (int mt = 0; mt < 4; mt++) {
                const int row = m0 + wm + mt * 16 + tr;
                float2 v0, v1;
                v0.x = fmaf(acc[mt][nt][0], sb0.x, sb0.y);
                v0.y = fmaf(acc[mt][nt][1], sb1.x, sb1.y);
                v1.x = fmaf(acc[mt][nt][2], sb0.x, sb0.y);
                v1.y = fmaf(acc[mt][nt][3], sb1.x, sb1.y);
                *reinterpret_cast<float2*>(out + (size_t)row * OUT_F + col) = v0;
                *reinterpret_cast<float2*>(out + (size_t)(row + 8) * OUT_F + col) = v1;
                acc[mt][nt][0] = 0.f; acc[mt][nt][1] = 0.f;
                acc[mt][nt][2] = 0.f; acc[mt][nt][3] = 0.f;
            }
        }

        if (tn >= TOTAL_TILES) break;
        t = tn; m0 = m0n; n0 = n0n; tb = tb2;
    }
}

// ============================================================================
// Launcher — inputs identified by SIZE (element counts):
//   x: 33,554,432   weight_packed: 11,272,192   scale/bias: 11,008 each
// weight_packed element type detected on-device (uint8 / int32 / bf16).
// ============================================================================
extern "C" void kernel_launch(void* const* d_in, const int* in_sizes, int n_in,
                              void* d_out, int out_size) {
    int ix = -1, iw = -1, is1 = -1, is2 = -1;
    for (int i = 0; i < n_in; i++) {
        long v = in_sizes[i];
        if (v == (long)TOKENS * IN_F)           ix = i;
        else if (v == (long)OUT_F * (IN_F / 4)) iw = i;
        else if (is1 < 0)                       is1 = i;
        else                                    is2 = i;
    }
    if (ix < 0) ix = 0;
    if (iw < 0) iw = 1;
    if (is1 < 0) is1 = 2;
    if (is2 < 0) is2 = 3;

    const float* x    = (const float*)d_in[ix];
    const void* wp    = d_in[iw];
    const float* c0   = (const float*)d_in[is1];
    const float* c1   = (const float*)d_in[is2];
    float* out        = (float*)d_out;

    prep_all_kernel<<<PREP_BLOCKS, 256>>>(x, wp, c0, c1);

    cudaFuncSetAttribute(ternary_gemm_kernel,
                         cudaFuncAttributeMaxDynamicSharedMemorySize, SMEM_BYTES);
    ternary_gemm_kernel<<<GRID_GEMM, 256, SMEM_BYTES>>>(out);
}

// round 17
// speedup vs baseline: 1.0952x; 1.0920x over previous
#include <cuda_runtime.h>
#include <cuda_fp16.h>
#include <cuda_bf16.h>
#include <cstdint>

// ============================================================================
// Problem constants
// ============================================================================
#define IN_F   4096
#define OUT_F  11008
#define TOKENS 8192

#define BM 128
#define BN 128
#define BK 64
#define KITERS (IN_F / BK)   // 64
#define STAGES 3
#define STAGE_BYTES 16384                  // 128 rows x 128B
#define OFF_B (STAGES * STAGE_BYTES)       // 49152
#define SMEM_BYTES (2 * STAGES * STAGE_BYTES + 1024)   // 99328

#define N_TILES (OUT_F / BN)   // 86
#define M_TILES (TOKENS / BM)  // 64
#define GROUP_N 8              // N-tiles per rasterization group

// Fused prep grid split
#define PX_BLOCKS 16384
#define PW_BLOCKS 11008
#define SB_BLOCKS 43
#define PREP_BLOCKS (PX_BLOCKS + PW_BLOCKS + SB_BLOCKS)

// __device__ scratch (allowed; no allocs)
__device__ __half X16g[(size_t)TOKENS * IN_F];   // 64 MB fp16 activations
__device__ __half W16g[(size_t)OUT_F * IN_F];    // 86 MB fp16 unpacked weights
__device__ float2 SBg[OUT_F];                    // packed (scale, bias)

// ============================================================================
// Helpers
// ============================================================================
__device__ __forceinline__ uint32_t smem_to_u32(const void* smem_ptr) {
    uint32_t addr;
    asm("{ .reg .u64 tmp; cvta.to.shared.u64 tmp, %1; cvt.u32.u64 %0, tmp; }"
        : "=r"(addr) : "l"(smem_ptr));
    return addr;
}

__device__ __forceinline__ uint32_t sw128(uint32_t off) {
    return off ^ ((off >> 3) & 0x70);
}

__device__ __forceinline__ void cp_async16(uint32_t smem_addr, const void* gptr) {
    size_t gaddr = __cvta_generic_to_global(gptr);
    asm volatile("cp.async.cg.shared.global [%0], [%1], 16;"
                 :: "r"(smem_addr), "l"(gaddr) : "memory");
}
#define CP_COMMIT()  asm volatile("cp.async.commit_group;" ::: "memory")
#define CP_WAIT_0()  asm volatile("cp.async.wait_group 0;" ::: "memory")
#define CP_WAIT_1()  asm volatile("cp.async.wait_group 1;" ::: "memory")

__device__ __forceinline__ void ldsm_x4(uint32_t* r, uint32_t addr) {
    asm volatile("ldmatrix.sync.aligned.m8n8.x4.shared.b16 {%0,%1,%2,%3}, [%4];"
                 : "=r"(r[0]), "=r"(r[1]), "=r"(r[2]), "=r"(r[3]) : "r"(addr));
}

__device__ __forceinline__ void mma16816(float* d, const uint32_t* a, const uint32_t* b) {
    asm volatile(
        "mma.sync.aligned.m16n8k16.row.col.f32.f16.f16.f32 "
        "{%0,%1,%2,%3}, {%4,%5,%6,%7}, {%8,%9}, {%0,%1,%2,%3};"
        : "+f"(d[0]), "+f"(d[1]), "+f"(d[2]), "+f"(d[3])
        : "r"(a[0]), "r"(a[1]), "r"(a[2]), "r"(a[3]), "r"(b[0]), "r"(b[1]));
}

// ============================================================================
// Fused prep kernel: one launch does x-convert, w-unpack, and SB table.
// ============================================================================
__global__ void __launch_bounds__(256)
prep_all_kernel(const float* __restrict__ x,
                const void* __restrict__ wp,
                const float* __restrict__ c0,
                const float* __restrict__ c1) {
    const int b = blockIdx.x;
    if (b < PX_BLOCKS) {
        size_t i = (size_t)b * 256 + threadIdx.x;
        const float4* src = (const float4*)x;
        float4 a = src[i * 2 + 0];
        float4 bb = src[i * 2 + 1];
        __half2 h0 = __floats2half2_rn(a.x, a.y);
        __half2 h1 = __floats2half2_rn(a.z, a.w);
        __half2 h2 = __floats2half2_rn(bb.x, bb.y);
        __half2 h3 = __floats2half2_rn(bb.z, bb.w);
        uint4 o;
        o.x = *reinterpret_cast<unsigned*>(&h0);
        o.y = *reinterpret_cast<unsigned*>(&h1);
        o.z = *reinterpret_cast<unsigned*>(&h2);
        o.w = *reinterpret_cast<unsigned*>(&h3);
        reinterpret_cast<uint4*>(X16g)[i] = o;
    } else if (b < PX_BLOCKS + PW_BLOCKS) {
        // detect weight layout (redundant per block):
        //  int32-widened: all u32 words < 256; bf16-widened: high byte of each
        //  half in {0, 0x3F..0x43}; uint8 raw: neither.
        const unsigned* w32 = (const unsigned*)wp;
        bool all_small = true, all_bf16 = true;
        for (int i = 0; i < 64; i++) {
            unsigned w = w32[i];
            if (w >= 256u) all_small = false;
            unsigned hb0 = (w >> 8) & 0xFFu;
            unsigned hb1 = (w >> 24) & 0xFFu;
            bool ok0 = (hb0 == 0u) || (hb0 >= 0x3Fu && hb0 <= 0x43u);
            bool ok1 = (hb1 == 0u) || (hb1 >= 0x3Fu && hb1 <= 0x43u);
            if (!(ok0 && ok1)) all_bf16 = false;
        }
        const int layout = all_small ? 1 : (all_bf16 ? 2 : 0);

        size_t i = (size_t)(b - PX_BLOCKS) * 256 + threadIdx.x;
        unsigned bytes4;
        if (layout == 1) {
            int4 v = reinterpret_cast<const int4*>(wp)[i];
            bytes4 = (unsigned)(v.x & 0xFF) | ((unsigned)(v.y & 0xFF) << 8) |
                     ((unsigned)(v.z & 0xFF) << 16) | ((unsigned)(v.w & 0xFF) << 24);
        } else if (layout == 2) {
            const __nv_bfloat16* p = reinterpret_cast<const __nv_bfloat16*>(wp) + 4 * i;
            unsigned b0 = (unsigned)__bfloat162float(p[0]);
            unsigned b1 = (unsigned)__bfloat162float(p[1]);
            unsigned b2 = (unsigned)__bfloat162float(p[2]);
            unsigned b3 = (unsigned)__bfloat162float(p[3]);
            bytes4 = b0 | (b1 << 8) | (b2 << 16) | (b3 << 24);
        } else {
            bytes4 = reinterpret_cast<const unsigned*>(wp)[i];
        }
        unsigned r32[8];
#pragma unroll
        for (int j = 0; j < 8; j++) {
            int v0 = (int)((bytes4 >> (4 * j)) & 3u) - 1;
            int v1 = (int)((bytes4 >> (4 * j + 2)) & 3u) - 1;
            __half2 ph = __halves2half2(__int2half_rn(v0), __int2half_rn(v1));
            r32[j] = *reinterpret_cast<unsigned*>(&ph);
        }
        uint4* dst = reinterpret_cast<uint4*>(W16g);
        dst[i * 2 + 0] = make_uint4(r32[0], r32[1], r32[2], r32[3]);
        dst[i * 2 + 1] = make_uint4(r32[4], r32[5], r32[6], r32[7]);
    } else {
        // scale/bias disambiguation (scale ~ U[0.01,0.1] all-positive)
        int pos = 0;
        for (int i = 0; i < 256; i++) pos += (c0[i] > 0.0f) ? 1 : 0;
        const float* s = (pos == 256) ? c0 : c1;
        const float* bp = (pos == 256) ? c1 : c0;
        int i = (b - PX_BLOCKS - PW_BLOCKS) * 256 + threadIdx.x;
        if (i < OUT_F) SBg[i] = make_float2(s[i], bp[i]);
    }
}

// ============================================================================
// Main GEMM (R12 shape): ldmatrix + mma.sync m16n8k16, 3-stage cp.async.
//   256 threads = 8 warps (2 M x 4 N); warp tile 64x32; CTA tile 128x128x64.
//   Tweak vs R12: next-stage cp.async issued AFTER the first ks block so the
//   LDGSTS burst overlaps MMA issue instead of delaying the LDSM->HMMA chain.
// ============================================================================
__global__ void __launch_bounds__(256, 2)
ternary_gemm_kernel(float* __restrict__ out) {
    extern __shared__ char smem_raw[];
    uint32_t smem_u = smem_to_u32(smem_raw);
    uint32_t base = (smem_u + 1023u) & ~1023u;

    const int tid = threadIdx.x;
    const int wid = tid >> 5;
    const int lane = tid & 31;

    // Rasterization: groups of (64 M-tiles x up to 8 N-tiles), M fastest.
    const int bid = blockIdx.x;
    const int group = bid >> 9;
    const int rem = bid - (group << 9);
    const int m_idx = rem & (M_TILES - 1);
    const int n_idx = group * GROUP_N + (rem >> 6);
    const int m0 = m_idx * BM;
    const int n0 = n_idx * BN;

    const int wm = (wid >> 2) * 64;
    const int wn = (wid & 3) * 32;

    // ldmatrix lane address components
    const int aRow = lane & 15;
    const int aC = lane >> 4;
    const int bRow = ((lane >> 4) << 3) + (lane & 7);
    const int bC = (lane >> 3) & 1;

    uint32_t rowOffA[4], rowOffB[2];
#pragma unroll
    for (int mt = 0; mt < 4; mt++) rowOffA[mt] = (uint32_t)(wm + mt * 16 + aRow) * 128u;
#pragma unroll
    for (int np = 0; np < 2; np++) rowOffB[np] = (uint32_t)(wn + np * 16 + bRow) * 128u;

    float acc[4][4][4];
#pragma unroll
    for (int mt = 0; mt < 4; mt++)
#pragma unroll
        for (int nt = 0; nt < 4; nt++)
#pragma unroll
            for (int r = 0; r < 4; r++) acc[mt][nt][r] = 0.f;

    // cp.async loader: 4 A-chunks + 4 B-chunks (16B) per thread per stage
    const int lrow = tid >> 3;
    const int lc = tid & 7;
    const __half* aGbase = X16g + (size_t)(m0 + lrow) * IN_F + lc * 8;
    const __half* bGbase = W16g + (size_t)(n0 + lrow) * IN_F + lc * 8;

    auto load_stage = [&](int it) {
        const int s = it % STAGES;
        const int k0 = it * BK;
        const uint32_t aB = base + s * STAGE_BYTES;
        const uint32_t bB = base + OFF_B + s * STAGE_BYTES;
#pragma unroll
        for (int j = 0; j < 4; j++) {
            uint32_t soff = sw128((uint32_t)(lrow + 32 * j) * 128u + (uint32_t)lc * 16u);
            cp_async16(aB + soff, aGbase + (size_t)(32 * j) * IN_F + k0);
            cp_async16(bB + soff, bGbase + (size_t)(32 * j) * IN_F + k0);
        }
        CP_COMMIT();
    };

    load_stage(0);
    load_stage(1);

    for (int i = 0; i < KITERS; i++) {
        if (i + 2 < KITERS) { CP_WAIT_1(); } else { CP_WAIT_0(); }
        __syncthreads();

        const int s = i % STAGES;
        const uint32_t aB = base + s * STAGE_BYTES;
        const uint32_t bB = base + OFF_B + s * STAGE_BYTES;

#pragma unroll
        for (int ks = 0; ks < BK / 16; ks++) {
            uint32_t af[4][4];
#pragma unroll
            for (int mt = 0; mt < 4; mt++)
                ldsm_x4(af[mt], aB + sw128(rowOffA[mt] + (uint32_t)(ks * 2 + aC) * 16u));
            uint32_t bf[2][4];
#pragma unroll
            for (int np = 0; np < 2; np++)
                ldsm_x4(bf[np], bB + sw128(rowOffB[np] + (uint32_t)(ks * 2 + bC) * 16u));
#pragma unroll
            for (int mt = 0; mt < 4; mt++)
#pragma unroll
                for (int nt = 0; nt < 4; nt++)
                    mma16816(acc[mt][nt], af[mt], &bf[nt >> 1][(nt & 1) * 2]);

            // issue next-stage loads after the first ks block: overlaps the
            // LDGSTS burst with MMA issue instead of the critical LDSM chain
            if (ks == 0 && i + 2 < KITERS) load_stage(i + 2);
        }
    }

    // Epilogue: y = d * scale[col] + bias[col]
    const int tr = lane >> 2;
    const int tc = (lane & 3) * 2;
#pragma unroll
    for (int nt = 0; nt < 4; nt++) {
        const int col = n0 + wn + nt * 8 + tc;
        const float2 sb0 = SBg[col];
        const float2 sb1 = SBg[col + 1];
#pragma unroll
        for (int mt = 0; mt < 4; mt++) {
            const int row = m0 + wm + mt * 16 + tr;
            float2 v0, v1;
            v0.x = fmaf(acc[mt][nt][0], sb0.x, sb0.y);
            v0.y = fmaf(acc[mt][nt][1], sb1.x, sb1.y);
            v1.x = fmaf(acc[mt][nt][2], sb0.x, sb0.y);
            v1.y = fmaf(acc[mt][nt][3], sb1.x, sb1.y);
            *reinterpret_cast<float2*>(out + (size_t)row * OUT_F + col) = v0;
            *reinterpret_cast<float2*>(out + (size_t)(row + 8) * OUT_F + col) = v1;
        }
    }
}

// ============================================================================
// Launcher — inputs identified by SIZE (element counts):
//   x: 33,554,432   weight_packed: 11,272,192   scale/bias: 11,008 each
// weight_packed element type detected on-device (uint8 / int32 / bf16).
// ============================================================================
extern "C" void kernel_launch(void* const* d_in, const int* in_sizes, int n_in,
                              void* d_out, int out_size) {
    int ix = -1, iw = -1, is1 = -1, is2 = -1;
    for (int i = 0; i < n_in; i++) {
        long v = in_sizes[i];
        if (v == (long)TOKENS * IN_F)           ix = i;
        else if (v == (long)OUT_F * (IN_F / 4)) iw = i;
        else if (is1 < 0)                       is1 = i;
        else                                    is2 = i;
    }
    if (ix < 0) ix = 0;
    if (iw < 0) iw = 1;
    if (is1 < 0) is1 = 2;
    if (is2 < 0) is2 = 3;

    const float* x    = (const float*)d_in[ix];
    const void* wp    = d_in[iw];
    const float* c0   = (const float*)d_in[is1];
    const float* c1   = (const float*)d_in[is2];
    float* out        = (float*)d_out;

    prep_all_kernel<<<PREP_BLOCKS, 256>>>(x, wp, c0, c1);

    cudaFuncSetAttribute(ternary_gemm_kernel,
                         cudaFuncAttributeMaxDynamicSharedMemorySize, SMEM_BYTES);
    ternary_gemm_kernel<<<M_TILES * N_TILES, 256, SMEM_BYTES>>>(out);
}